// round 3
// baseline (speedup 1.0000x reference)
#include <cuda_runtime.h>
#include <cstdint>

#define MARGIN 0.3f
#define EPSV   1e-6f

#define MAX_B 8192
#define MAX_L 4096
#define INF_I 0x7fffffff

__device__ int2  g_pair[MAX_B];     // per-anchor {pos_idx, neg_idx} (INF_I = none)
__device__ float g_loss[MAX_B];     // per-anchor triplet loss
__device__ int   g_valid[MAX_B];    // per-anchor validity
__device__ int   g_done;            // completion ticket for tail reduction

__device__ __forceinline__ int read_label(const void* lab, int i, int is64) {
    if (is64) return (int)((const long long*)lab)[i];
    return ((const int*)lab)[i];
}

// ================================================================ kernel A
// One block. Shared-memory label tables; resolves per-anchor pos/neg indices.
__global__ void k_labels(const void* __restrict__ labels, int B) {
    __shared__ int s_min1[MAX_L];
    __shared__ int s_min2[MAX_L];
    __shared__ int s_flag;   // any nonzero odd 32-bit word -> labels are int32
    __shared__ int s_diff;   // first index whose label != labels[0]
    int t = threadIdx.x;
    int nt = blockDim.x;

    for (int j = t; j < MAX_L; j += nt) { s_min1[j] = INF_I; s_min2[j] = INF_I; }
    if (t == 0) { s_flag = 0; s_diff = INF_I; g_done = 0; }
    __syncthreads();

    // dtype detect: odd word indices < B are high halves of int64 (all zero for
    // labels < 2^32) or independent int32 labels (essentially never all zero).
    const int* w = (const int*)labels;
    for (int i = 2 * t + 1; i < B; i += 2 * nt)
        if (w[i] != 0) atomicOr(&s_flag, 1);
    __syncthreads();
    int is64 = (s_flag == 0);
    int l0 = read_label(labels, 0, is64);

    // pass 1: first occurrence per label; first differing index
    for (int i = t; i < B; i += nt) {
        int li = read_label(labels, i, is64);
        if (li >= 0 && li < MAX_L) atomicMin(&s_min1[li], i);
        if (li != l0) atomicMin(&s_diff, i);
    }
    __syncthreads();

    // pass 2: second occurrence per label
    for (int i = t; i < B; i += nt) {
        int li = read_label(labels, i, is64);
        if (li >= 0 && li < MAX_L && s_min1[li] != i) atomicMin(&s_min2[li], i);
    }
    __syncthreads();

    // resolve per-anchor pos/neg
    for (int i = t; i < B; i += nt) {
        int li = read_label(labels, i, is64);
        int p = (li >= 0 && li < MAX_L) ? s_min1[li] : INF_I;
        if (p == i) p = s_min2[li];
        int n = (li != l0) ? 0 : s_diff;
        g_pair[i] = make_int2(p, n);
    }
}

// ================================================================ kernel B
// Warp per anchor + fused deterministic tail reduction (last block).
__global__ void k_dist(const float* __restrict__ features,
                       float* __restrict__ out, int B, int D) {
    __shared__ int s_ticket;
    int warp = (blockIdx.x * blockDim.x + threadIdx.x) >> 5;
    int lane = threadIdx.x & 31;

    if (warp < B) {
        int2 pn = g_pair[warp];
        if (pn.x != INF_I && pn.y != INF_I) {
            const float4* __restrict__ A = (const float4*)(features + (size_t)warp * D);
            const float4* __restrict__ P = (const float4*)(features + (size_t)pn.x * D);
            const float4* __restrict__ N = (const float4*)(features + (size_t)pn.y * D);
            int nv = D >> 2;
            float sap = 0.0f, san = 0.0f;
            #pragma unroll 8
            for (int k = lane; k < nv; k += 32) {
                float4 a  = A[k];
                float4 pp = P[k];
                float4 nn = N[k];
                float d;
                d = a.x - pp.x + EPSV; sap = fmaf(d, d, sap);
                d = a.y - pp.y + EPSV; sap = fmaf(d, d, sap);
                d = a.z - pp.z + EPSV; sap = fmaf(d, d, sap);
                d = a.w - pp.w + EPSV; sap = fmaf(d, d, sap);
                d = a.x - nn.x + EPSV; san = fmaf(d, d, san);
                d = a.y - nn.y + EPSV; san = fmaf(d, d, san);
                d = a.z - nn.z + EPSV; san = fmaf(d, d, san);
                d = a.w - nn.w + EPSV; san = fmaf(d, d, san);
            }
            #pragma unroll
            for (int off = 16; off > 0; off >>= 1) {
                sap += __shfl_down_sync(0xffffffffu, sap, off);
                san += __shfl_down_sync(0xffffffffu, san, off);
            }
            if (lane == 0) {
                g_loss[warp]  = fmaxf(sqrtf(sap) - sqrtf(san) + MARGIN, 0.0f);
                g_valid[warp] = 1;
            }
        } else if (lane == 0) {
            g_loss[warp] = 0.0f;
            g_valid[warp] = 0;
        }
    }

    // ---- last-block-done deterministic reduction ----
    __threadfence();
    __syncthreads();
    if (threadIdx.x == 0) s_ticket = atomicAdd(&g_done, 1);
    __syncthreads();
    if (s_ticket != (int)gridDim.x - 1) return;

    __shared__ float s_sum[256];
    __shared__ int   s_cnt[256];
    int t = threadIdx.x;
    float sum = 0.0f;
    int cnt = 0;
    for (int i = t; i < B; i += blockDim.x) {
        sum += g_loss[i];
        cnt += g_valid[i];
    }
    s_sum[t] = sum;
    s_cnt[t] = cnt;
    __syncthreads();
    for (int off = (int)blockDim.x >> 1; off > 0; off >>= 1) {
        if (t < off) {
            s_sum[t] += s_sum[t + off];
            s_cnt[t] += s_cnt[t + off];
        }
        __syncthreads();
    }
    if (t == 0) {
        int c = s_cnt[0];
        out[0] = (c > 0) ? (s_sum[0] / (float)c) : 0.0f;
    }
}

// ================================================================ launch
extern "C" void kernel_launch(void* const* d_in, const int* in_sizes, int n_in,
                              void* d_out, int out_size) {
    int i_feat = (in_sizes[0] >= in_sizes[1]) ? 0 : 1;
    int i_lab  = 1 - i_feat;
    const float* features = (const float*)d_in[i_feat];
    const void*  labels   = d_in[i_lab];
    int B = in_sizes[i_lab];
    int D = in_sizes[i_feat] / B;

    k_labels<<<1, 1024>>>(labels, B);
    k_dist  <<<(B + 7) / 8, 256>>>(features, (float*)d_out, B, D);
}